// round 10
// baseline (speedup 1.0000x reference)
#include <cuda_runtime.h>
#include <cuda_bf16.h>
#include <cstdint>
#include <cstddef>

// Problem constants
#define BB   32
#define NN   128
#define IND  32
#define OUTD 64

// Scratch (device globals; no allocs allowed)
__device__ __nv_bfloat16 g_s1[(size_t)BB * OUTD * NN * NN];  // X1: [b,e,i,k]
__device__ __nv_bfloat16 g_s2[(size_t)BB * OUTD * NN * NN];  // X2^T: [b,e,j,k]

__device__ __forceinline__ uint32_t smem_u32(const void* p) {
    uint32_t a;
    asm("{ .reg .u64 t; cvta.to.shared.u64 t, %1; cvt.u32.u64 %0, t; }"
        : "=r"(a) : "l"(p));
    return a;
}
__device__ __forceinline__ uint64_t pack_dup(float x) {
    uint64_t d; uint32_t u = __float_as_uint(x);
    asm("mov.b64 %0, {%1, %1};" : "=l"(d) : "r"(u));
    return d;
}
__device__ __forceinline__ void fma2(uint64_t& d, uint64_t a, uint64_t b) {
    asm("fma.rn.f32x2 %0, %1, %2, %0;" : "+l"(d) : "l"(a), "l"(b));
}
__device__ __forceinline__ void unpack2(float& lo, float& hi, uint64_t v) {
    uint32_t l, h;
    asm("mov.b64 {%0, %1}, %2;" : "=r"(l), "=r"(h) : "l"(v));
    lo = __uint_as_float(l); hi = __uint_as_float(h);
}

// ---------------------------------------------------------------------------
// Fused MLP (both passes in one grid), inner product via packed f32x2 FMA.
// pass=0: block=(b,p) computes X1[b,p,t,e]  -> s1[b,e,p,t]   (K-major A)
// pass=1: block=(b,q) computes X2[b,t,q,e]  -> s2[b,e,q,t]   (K-major B^T)
// Grid 8192 (pass = blockIdx.x>>12), 128 threads.
// ---------------------------------------------------------------------------
__global__ void __launch_bounds__(128) mlp_kernel(
    const float* __restrict__ X,
    const float* __restrict__ W1, const float* __restrict__ b1,
    const float* __restrict__ W2, const float* __restrict__ b2,
    const int* __restrict__ nn32,
    __nv_bfloat16* __restrict__ s1, __nv_bfloat16* __restrict__ s2)
{
    __shared__ float Xs[IND][NN];    // [k][t]
    __shared__ float Ws[IND][OUTD];  // [k][e]
    __shared__ float bs[OUTD];

    const int pass = blockIdx.x >> 12;
    const int blk  = blockIdx.x & 4095;
    const int b    = blk >> 7;
    const int row  = blk & 127;
    const int tid  = threadIdx.x;

    const float* __restrict__ W    = pass ? W2 : W1;
    const float* __restrict__ bias = pass ? b2 : b1;
    __nv_bfloat16* __restrict__ dst = pass ? s2 : s1;

    for (int l = tid; l < IND * OUTD; l += 128) Ws[l >> 6][l & 63] = W[l];
    if (tid < OUTD) bs[tid] = bias[tid];

    {   // load this block's 128 X tuple-rows (128B each), transposed into Xs[k][t]
        const int t = tid;
        const size_t xoff = pass ? (((size_t)b * NN + t) * NN + row) * IND
                                 : (((size_t)b * NN + row) * NN + t) * IND;
        const float4* Xp = reinterpret_cast<const float4*>(X + xoff);
#pragma unroll
        for (int c = 0; c < 8; c++) {
            float4 v = Xp[c];
            Xs[4 * c + 0][t] = v.x; Xs[4 * c + 1][t] = v.y;
            Xs[4 * c + 2][t] = v.z; Xs[4 * c + 3][t] = v.w;
        }
    }
    __syncthreads();

    const int n = (nn32[1] == 0) ? nn32[2 * b] : nn32[b];   // int64 vs int32 defense

    const int tx = tid & 31;   // t = 4*tx + i
    const int ty = tid >> 5;   // e = 16*ty + j  (j = 2*j2 + half)

    // acc2[i][j2]: packed pair (e even, e odd)
    uint64_t acc2[4][8];
    {
        const ulonglong2* bp = reinterpret_cast<const ulonglong2*>(&bs[16 * ty]);
        ulonglong2 q0 = bp[0], q1 = bp[1], q2 = bp[2], q3 = bp[3];
        uint64_t binit[8] = {q0.x, q0.y, q1.x, q1.y, q2.x, q2.y, q3.x, q3.y};
#pragma unroll
        for (int i = 0; i < 4; i++)
#pragma unroll
            for (int j2 = 0; j2 < 8; j2++) acc2[i][j2] = binit[j2];
    }

#pragma unroll 4
    for (int k = 0; k < IND; k++) {
        float4 av = *reinterpret_cast<const float4*>(&Xs[k][4 * tx]);
        uint64_t ad[4] = {pack_dup(av.x), pack_dup(av.y),
                          pack_dup(av.z), pack_dup(av.w)};
        const ulonglong2* Wp = reinterpret_cast<const ulonglong2*>(&Ws[k][16 * ty]);
        ulonglong2 w0 = Wp[0], w1 = Wp[1], w2 = Wp[2], w3 = Wp[3];
        uint64_t wv[8] = {w0.x, w0.y, w1.x, w1.y, w2.x, w2.y, w3.x, w3.y};
#pragma unroll
        for (int i = 0; i < 4; i++)
#pragma unroll
            for (int j2 = 0; j2 < 8; j2++)
                fma2(acc2[i][j2], ad[i], wv[j2]);
    }

    const bool rok = row < n;
    float m[4];
#pragma unroll
    for (int i = 0; i < 4; i++) m[i] = (rok && (4 * tx + i) < n) ? 1.0f : 0.0f;

#pragma unroll
    for (int j2 = 0; j2 < 8; j2++) {
        float vlo[4], vhi[4];
#pragma unroll
        for (int i = 0; i < 4; i++) {
            unpack2(vlo[i], vhi[i], acc2[i][j2]);
            vlo[i] = fmaxf(vlo[i], 0.0f) * m[i];
            vhi[i] = fmaxf(vhi[i], 0.0f) * m[i];
        }
        const int e0 = 16 * ty + 2 * j2;
        __nv_bfloat16* d0 = dst + ((size_t)(b * OUTD + e0)) * (NN * NN)
                                + (size_t)row * NN + 4 * tx;
        __nv_bfloat16* d1 = d0 + (size_t)(NN * NN);
        __nv_bfloat162 l0 = __floats2bfloat162_rn(vlo[0], vlo[1]);
        __nv_bfloat162 l1 = __floats2bfloat162_rn(vlo[2], vlo[3]);
        __nv_bfloat162 h0 = __floats2bfloat162_rn(vhi[0], vhi[1]);
        __nv_bfloat162 h1 = __floats2bfloat162_rn(vhi[2], vhi[3]);
        uint2 pl, ph;
        pl.x = *reinterpret_cast<uint32_t*>(&l0);
        pl.y = *reinterpret_cast<uint32_t*>(&l1);
        ph.x = *reinterpret_cast<uint32_t*>(&h0);
        ph.y = *reinterpret_cast<uint32_t*>(&h1);
        *reinterpret_cast<uint2*>(d0) = pl;
        *reinterpret_cast<uint2*>(d1) = ph;
    }
}

// ---------------------------------------------------------------------------
// Stage 2: 2048 x [128x128x128] bf16 mma.sync GEMMs, one CTA per (b,e),
// clusters of 8 = one e-octet of the same b. 512 threads (16 warps, 32x32
// warp tiles) for 50% occupancy. DSMEM exchange assembles out[b,i,j,e0:e0+8].
// ---------------------------------------------------------------------------
#define APITCH 136                       // bf16/row: 272B, 16B-aligned, LDSM conflict-free
#define S2_B_OFF (NN * APITCH * 2)       // 34816 B
#define CPITCH 132                       // fp32/row for C staging
#define S2_SMEM (2 * NN * APITCH * 2)    // 69632 B (>= C staging 67584)
#define CLU 8

__device__ __forceinline__ void ldsm_x4(uint32_t& r0, uint32_t& r1,
                                        uint32_t& r2, uint32_t& r3, uint32_t a) {
    asm volatile("ldmatrix.sync.aligned.m8n8.x4.shared.b16 {%0,%1,%2,%3}, [%4];"
                 : "=r"(r0), "=r"(r1), "=r"(r2), "=r"(r3) : "r"(a));
}
__device__ __forceinline__ void mma_bf16(float* c, const uint32_t* a,
                                         uint32_t b0, uint32_t b1) {
    asm volatile(
        "mma.sync.aligned.m16n8k16.row.col.f32.bf16.bf16.f32 "
        "{%0,%1,%2,%3}, {%4,%5,%6,%7}, {%8,%9}, {%0,%1,%2,%3};"
        : "+f"(c[0]), "+f"(c[1]), "+f"(c[2]), "+f"(c[3])
        : "r"(a[0]), "r"(a[1]), "r"(a[2]), "r"(a[3]), "r"(b0), "r"(b1));
}
__device__ __forceinline__ float4 dsmem_ld4(uint32_t local_addr, uint32_t rank) {
    uint32_t r; float4 v;
    asm volatile("mapa.shared::cluster.u32 %0, %1, %2;"
                 : "=r"(r) : "r"(local_addr), "r"(rank));
    asm volatile("ld.shared::cluster.v4.f32 {%0,%1,%2,%3}, [%4];"
                 : "=f"(v.x), "=f"(v.y), "=f"(v.z), "=f"(v.w) : "r"(r));
    return v;
}

__global__ void __launch_bounds__(512, 2) stage2_kernel(float* __restrict__ out)
{
    extern __shared__ char sm[];
    const uint32_t smb = smem_u32(sm);
    const int tid  = threadIdx.x;
    const int wid  = tid >> 5;
    const int lane = tid & 31;
    const int be   = blockIdx.x;
    const int b    = be >> 6;
    uint32_t rank;
    asm("mov.u32 %0, %%cluster_ctarank;" : "=r"(rank));

    // ---- Load A and B tiles (64KB each bf16) into padded smem ----
    const uint4* A4 = reinterpret_cast<const uint4*>(g_s1 + (size_t)be * (NN * NN));
    const uint4* B4 = reinterpret_cast<const uint4*>(g_s2 + (size_t)be * (NN * NN));
#pragma unroll
    for (int it = 0; it < 4; it++) {
        const int l = it * 512 + tid;          // 2048 uint4 per operand
        const int r = l >> 4, c8 = l & 15;
        const uint32_t o = (uint32_t)r * (APITCH * 2) + (uint32_t)c8 * 16;
        *reinterpret_cast<uint4*>(sm + o)            = A4[l];
        *reinterpret_cast<uint4*>(sm + S2_B_OFF + o) = B4[l];
    }
    __syncthreads();

    const int warp_m = wid >> 2;   // 0..3 : rows warp_m*32
    const int warp_n = wid & 3;    // 0..3 : cols warp_n*32

    float acc[2][4][4];
#pragma unroll
    for (int mt = 0; mt < 2; mt++)
#pragma unroll
        for (int nt = 0; nt < 4; nt++)
#pragma unroll
            for (int r = 0; r < 4; r++) acc[mt][nt][r] = 0.0f;

    const int a_row = (lane & 15);
    const int a_kof = (lane >> 4) * 8;
    const int b_nl  = (lane & 7) + ((lane >> 4) << 3);
    const int b_kof = ((lane >> 3) & 1) * 8;

#pragma unroll
    for (int kk = 0; kk < 8; kk++) {
        const int k0 = kk * 16;
        uint32_t a[2][4];
#pragma unroll
        for (int mt = 0; mt < 2; mt++) {
            uint32_t ad = smb + (uint32_t)(warp_m * 32 + mt * 16 + a_row) * (APITCH * 2)
                              + (uint32_t)(k0 + a_kof) * 2;
            ldsm_x4(a[mt][0], a[mt][1], a[mt][2], a[mt][3], ad);
        }
        uint32_t bfr[2][4];
#pragma unroll
        for (int np = 0; np < 2; np++) {
            uint32_t bd = smb + S2_B_OFF
                        + (uint32_t)(warp_n * 32 + np * 16 + b_nl) * (APITCH * 2)
                        + (uint32_t)(k0 + b_kof) * 2;
            ldsm_x4(bfr[np][0], bfr[np][1], bfr[np][2], bfr[np][3], bd);
        }
#pragma unroll
        for (int mt = 0; mt < 2; mt++)
#pragma unroll
            for (int nt = 0; nt < 4; nt++)
                mma_bf16(acc[mt][nt], a[mt],
                         bfr[nt >> 1][(nt & 1) * 2 + 0],
                         bfr[nt >> 1][(nt & 1) * 2 + 1]);
    }
    __syncthreads();   // done reading A/B; reuse smem for C

    // ---- Stage C into own smem [128][CPITCH] ----
    float* Cs = reinterpret_cast<float*>(sm);
#pragma unroll
    for (int mt = 0; mt < 2; mt++) {
        const int mrow = warp_m * 32 + mt * 16 + (lane >> 2);
#pragma unroll
        for (int nt = 0; nt < 4; nt++) {
            const int ncol = warp_n * 32 + nt * 8 + (lane & 3) * 2;
            *reinterpret_cast<float2*>(&Cs[mrow * CPITCH + ncol]) =
                make_float2(acc[mt][nt][0], acc[mt][nt][1]);
            *reinterpret_cast<float2*>(&Cs[(mrow + 8) * CPITCH + ncol]) =
                make_float2(acc[mt][nt][2], acc[mt][nt][3]);
        }
    }

    // ---- Cluster barrier: all 8 siblings' C tiles ready ----
    asm volatile("barrier.cluster.arrive.aligned;" ::: "memory");
    asm volatile("barrier.cluster.wait.aligned;" ::: "memory");

    // ---- DSMEM exchange: rank owns i in [16*rank, 16*rank+16).
    const int e_base = (be & ~(CLU - 1)) & 63;      // e octet base
    {
        const int iloc = tid >> 5;                  // 0..15
        const int j0   = (tid & 31) * 4;            // 0,4,..,124
        const int i    = (int)rank * 16 + iloc;
        const uint32_t laddr = smb + (uint32_t)(i * CPITCH + j0) * 4;

        float4 c[CLU];
#pragma unroll
        for (int s = 0; s < CLU; s++) c[s] = dsmem_ld4(laddr, (uint32_t)s);

        float* op = out + (((size_t)b * NN + i) * NN + j0) * OUTD + e_base;
#pragma unroll
        for (int jj = 0; jj < 4; jj++) {
            float v[8] = {
                (&c[0].x)[jj], (&c[1].x)[jj], (&c[2].x)[jj], (&c[3].x)[jj],
                (&c[4].x)[jj], (&c[5].x)[jj], (&c[6].x)[jj], (&c[7].x)[jj]};
            float* o = op + (size_t)jj * OUTD;
            *reinterpret_cast<float4*>(o)     = make_float4(v[0], v[1], v[2], v[3]);
            *reinterpret_cast<float4*>(o + 4) = make_float4(v[4], v[5], v[6], v[7]);
        }
    }

    // ---- Protect smem until all siblings finished reading ----
    asm volatile("barrier.cluster.arrive.aligned;" ::: "memory");
    asm volatile("barrier.cluster.wait.aligned;" ::: "memory");
}

// ---------------------------------------------------------------------------
extern "C" void kernel_launch(void* const* d_in, const int* in_sizes, int n_in,
                              void* d_out, int out_size)
{
    const float* X  = (const float*)d_in[0];
    const float* W1 = (const float*)d_in[1];
    const float* b1 = (const float*)d_in[2];
    const float* W2 = (const float*)d_in[3];
    const float* b2 = (const float*)d_in[4];
    const int*   nn = (const int*)d_in[5];
    float* out = (float*)d_out;

    __nv_bfloat16 *s1, *s2;
    cudaGetSymbolAddress((void**)&s1, g_s1);
    cudaGetSymbolAddress((void**)&s2, g_s2);

    // Fused MLP (both passes, one grid)
    mlp_kernel<<<2 * BB * NN, 128>>>(X, W1, b1, W2, b2, nn, s1, s2);

    // Stage 2 as clusters of 8 (one e-octet per cluster)
    cudaFuncSetAttribute(stage2_kernel,
                         cudaFuncAttributeMaxDynamicSharedMemorySize, S2_SMEM);
    cudaLaunchConfig_t cfg = {};
    cfg.gridDim  = dim3(BB * OUTD, 1, 1);
    cfg.blockDim = dim3(512, 1, 1);
    cfg.dynamicSmemBytes = S2_SMEM;
    cudaLaunchAttribute attrs[1];
    attrs[0].id = cudaLaunchAttributeClusterDimension;
    attrs[0].val.clusterDim = {CLU, 1, 1};
    cfg.attrs = attrs;
    cfg.numAttrs = 1;
    cudaLaunchKernelEx(&cfg, stage2_kernel, out);
}

// round 11
// speedup vs baseline: 1.5393x; 1.5393x over previous
#include <cuda_runtime.h>
#include <cuda_bf16.h>
#include <cstdint>
#include <cstddef>

// Problem constants
#define BB   32
#define NN   128
#define IND  32
#define OUTD 64

// Scratch (device globals; no allocs allowed)
__device__ __nv_bfloat16 g_s1[(size_t)BB * OUTD * NN * NN];  // X1: [b,e,i,k]
__device__ __nv_bfloat16 g_s2[(size_t)BB * OUTD * NN * NN];  // X2^T: [b,e,j,k]

__device__ __forceinline__ uint32_t smem_u32(const void* p) {
    uint32_t a;
    asm("{ .reg .u64 t; cvta.to.shared.u64 t, %1; cvt.u32.u64 %0, t; }"
        : "=r"(a) : "l"(p));
    return a;
}
__device__ __forceinline__ float cvt_tf32(float x) {
    float r;
    asm("cvt.rna.tf32.f32 %0, %1;" : "=f"(r) : "f"(x));
    return r;
}
__device__ __forceinline__ void mma_tf32(float* c, const float* a,
                                         float b0, float b1) {
    asm volatile(
        "mma.sync.aligned.m16n8k8.row.col.f32.tf32.tf32.f32 "
        "{%0,%1,%2,%3}, {%4,%5,%6,%7}, {%8,%9}, {%0,%1,%2,%3};"
        : "+f"(c[0]), "+f"(c[1]), "+f"(c[2]), "+f"(c[3])
        : "f"(a[0]), "f"(a[1]), "f"(a[2]), "f"(a[3]), "f"(b0), "f"(b1));
}

// ---------------------------------------------------------------------------
// Fused MLP via tf32 tensor-core mma. Both passes in one grid.
// pass=0: block=(b,p), GEMM M=t(q tuples), writes X1 -> s1[b,e,p,t]
// pass=1: block=(b,q), GEMM M=t(p tuples), writes X2^T -> s2[b,e,q,t]
// Per block: [128 t x 32 k] @ [32 k x 64 e]. 4 warps, 32 rows each.
// Grid 8192 (pass = blockIdx.x>>12), 128 threads.
// ---------------------------------------------------------------------------
#define XP 36      // Xs pitch (floats): conflict-free frag gathers
#define WP 65      // Ws pitch (floats): conflict-free B gathers
#define CP 136     // Cs pitch (bf16): rows 272B -> 16B-aligned chunks

__global__ void __launch_bounds__(128) mlp_kernel(
    const float* __restrict__ X,
    const float* __restrict__ W1, const float* __restrict__ b1,
    const float* __restrict__ W2, const float* __restrict__ b2,
    const int* __restrict__ nn32,
    __nv_bfloat16* __restrict__ s1, __nv_bfloat16* __restrict__ s2)
{
    __shared__ float Ws[IND][WP];
    __shared__ float bs[OUTD];
    __shared__ char  ubuf[NN * XP * 4];          // Xs (18432B) / Cs (17408B)
    float*         Xs = reinterpret_cast<float*>(ubuf);
    __nv_bfloat16* Cs = reinterpret_cast<__nv_bfloat16*>(ubuf);

    const int pass = blockIdx.x >> 12;
    const int blk  = blockIdx.x & 4095;
    const int b    = blk >> 7;
    const int row  = blk & 127;
    const int tid  = threadIdx.x;
    const int wid  = tid >> 5;
    const int lane = tid & 31;

    const float* __restrict__ W    = pass ? W2 : W1;
    const float* __restrict__ bias = pass ? b2 : b1;
    __nv_bfloat16* __restrict__ dst = pass ? s2 : s1;

    for (int l = tid; l < IND * OUTD; l += 128)
        Ws[l >> 6][l & 63] = cvt_tf32(W[l]);
    if (tid < OUTD) bs[tid] = bias[tid];

    {   // load 128 tuple-rows, tf32-convert, into Xs[t][k]
        const int t = tid;
        const size_t xoff = pass ? (((size_t)b * NN + t) * NN + row) * IND
                                 : (((size_t)b * NN + row) * NN + t) * IND;
        const float4* Xp = reinterpret_cast<const float4*>(X + xoff);
#pragma unroll
        for (int c = 0; c < 8; c++) {
            float4 v = Xp[c];
            float* xr = Xs + t * XP + 4 * c;
            xr[0] = cvt_tf32(v.x); xr[1] = cvt_tf32(v.y);
            xr[2] = cvt_tf32(v.z); xr[3] = cvt_tf32(v.w);
        }
    }
    __syncthreads();

    const int n = (nn32[1] == 0) ? nn32[2 * b] : nn32[b];   // int64 vs int32 defense

    // ---- tf32 mma: warp owns rows 32*wid..+31 (2 m16 tiles), all 64 e ----
    float acc[2][8][4];
#pragma unroll
    for (int mt = 0; mt < 2; mt++)
#pragma unroll
        for (int nt = 0; nt < 8; nt++)
#pragma unroll
            for (int q = 0; q < 4; q++) acc[mt][nt][q] = 0.0f;

    const int lr = lane >> 2;    // 0..7
    const int lc = lane & 3;     // 0..3

#pragma unroll
    for (int ks = 0; ks < 4; ks++) {
        const int k0 = ks * 8;
        float a[2][4];
#pragma unroll
        for (int mt = 0; mt < 2; mt++) {
            const int r0 = 32 * wid + 16 * mt + lr;
            a[mt][0] = Xs[r0 * XP + k0 + lc];
            a[mt][1] = Xs[(r0 + 8) * XP + k0 + lc];
            a[mt][2] = Xs[r0 * XP + k0 + 4 + lc];
            a[mt][3] = Xs[(r0 + 8) * XP + k0 + 4 + lc];
        }
        float bfr[8][2];
#pragma unroll
        for (int nt = 0; nt < 8; nt++) {
            const int n0 = 8 * nt + lr;
            bfr[nt][0] = Ws[k0 + lc][n0];
            bfr[nt][1] = Ws[k0 + 4 + lc][n0];
        }
#pragma unroll
        for (int mt = 0; mt < 2; mt++)
#pragma unroll
            for (int nt = 0; nt < 8; nt++)
                mma_tf32(acc[mt][nt], a[mt], bfr[nt][0], bfr[nt][1]);
    }
    __syncthreads();   // done with Xs; reuse as Cs

    // ---- bias + ReLU + mask, stage bf16 into Cs[e][t] ----
    const bool rowok = row < n;
#pragma unroll
    for (int mt = 0; mt < 2; mt++) {
        const int r_lo = 32 * wid + 16 * mt + lr;
        const int r_hi = r_lo + 8;
        const float mlo = (rowok && r_lo < n) ? 1.0f : 0.0f;
        const float mhi = (rowok && r_hi < n) ? 1.0f : 0.0f;
#pragma unroll
        for (int nt = 0; nt < 8; nt++) {
            const int e0 = 8 * nt + 2 * lc;
            const float bb0 = bs[e0], bb1 = bs[e0 + 1];
            Cs[e0 * CP + r_lo]       = __float2bfloat16(fmaxf(acc[mt][nt][0] + bb0, 0.0f) * mlo);
            Cs[(e0 + 1) * CP + r_lo] = __float2bfloat16(fmaxf(acc[mt][nt][1] + bb1, 0.0f) * mlo);
            Cs[e0 * CP + r_hi]       = __float2bfloat16(fmaxf(acc[mt][nt][2] + bb0, 0.0f) * mhi);
            Cs[(e0 + 1) * CP + r_hi] = __float2bfloat16(fmaxf(acc[mt][nt][3] + bb1, 0.0f) * mhi);
        }
    }
    __syncthreads();

    // ---- coalesced gmem store: dst[b,e,row,t], 16B chunks ----
    __nv_bfloat16* dbase = dst + (size_t)(b * OUTD) * (NN * NN) + (size_t)row * NN;
#pragma unroll
    for (int it = 0; it < 8; it++) {
        const int u  = it * 128 + tid;        // 0..1023
        const int e  = u >> 4;
        const int c16 = u & 15;               // 16B chunk (8 bf16)
        *reinterpret_cast<uint4*>(dbase + (size_t)e * (NN * NN) + c16 * 8) =
            *reinterpret_cast<const uint4*>(Cs + e * CP + c16 * 8);
    }
}

// ---------------------------------------------------------------------------
// Stage 2 (exact R8 config): 2048 x [128x128x128] bf16 mma.sync GEMMs, one
// CTA per (b,e), clusters of 8 = one e-octet. 256 threads, 64x32 warp tiles.
// DSMEM exchange assembles out[b,i,j,e0:e0+8] directly.
// ---------------------------------------------------------------------------
#define APITCH 136                       // bf16/row: 272B, 16B-aligned, LDSM conflict-free
#define S2_B_OFF (NN * APITCH * 2)       // 34816 B
#define CPITCH 132                       // fp32/row for C staging
#define S2_SMEM (2 * NN * APITCH * 2)    // 69632 B (>= C staging 67584)
#define CLU 8

__device__ __forceinline__ void ldsm_x4(uint32_t& r0, uint32_t& r1,
                                        uint32_t& r2, uint32_t& r3, uint32_t a) {
    asm volatile("ldmatrix.sync.aligned.m8n8.x4.shared.b16 {%0,%1,%2,%3}, [%4];"
                 : "=r"(r0), "=r"(r1), "=r"(r2), "=r"(r3) : "r"(a));
}
__device__ __forceinline__ void mma_bf16(float* c, const uint32_t* a,
                                         uint32_t b0, uint32_t b1) {
    asm volatile(
        "mma.sync.aligned.m16n8k16.row.col.f32.bf16.bf16.f32 "
        "{%0,%1,%2,%3}, {%4,%5,%6,%7}, {%8,%9}, {%0,%1,%2,%3};"
        : "+f"(c[0]), "+f"(c[1]), "+f"(c[2]), "+f"(c[3])
        : "r"(a[0]), "r"(a[1]), "r"(a[2]), "r"(a[3]), "r"(b0), "r"(b1));
}
__device__ __forceinline__ float4 dsmem_ld4(uint32_t local_addr, uint32_t rank) {
    uint32_t r; float4 v;
    asm volatile("mapa.shared::cluster.u32 %0, %1, %2;"
                 : "=r"(r) : "r"(local_addr), "r"(rank));
    asm volatile("ld.shared::cluster.v4.f32 {%0,%1,%2,%3}, [%4];"
                 : "=f"(v.x), "=f"(v.y), "=f"(v.z), "=f"(v.w) : "r"(r));
    return v;
}

__global__ void __launch_bounds__(256, 1) stage2_kernel(float* __restrict__ out)
{
    extern __shared__ char sm[];
    const uint32_t smb = smem_u32(sm);
    const int tid  = threadIdx.x;
    const int wid  = tid >> 5;
    const int lane = tid & 31;
    const int be   = blockIdx.x;
    const int b    = be >> 6;
    uint32_t rank;
    asm("mov.u32 %0, %%cluster_ctarank;" : "=r"(rank));

    // ---- Load A and B tiles (64KB each bf16) into padded smem ----
    const uint4* A4 = reinterpret_cast<const uint4*>(g_s1 + (size_t)be * (NN * NN));
    const uint4* B4 = reinterpret_cast<const uint4*>(g_s2 + (size_t)be * (NN * NN));
#pragma unroll
    for (int it = 0; it < 8; it++) {
        const int l = it * 256 + tid;          // 2048 uint4 per operand
        const int r = l >> 4, c8 = l & 15;
        const uint32_t o = (uint32_t)r * (APITCH * 2) + (uint32_t)c8 * 16;
        *reinterpret_cast<uint4*>(sm + o)            = A4[l];
        *reinterpret_cast<uint4*>(sm + S2_B_OFF + o) = B4[l];
    }
    __syncthreads();

    const int warp_m = wid >> 2;   // rows warp_m*64
    const int warp_n = wid & 3;    // cols warp_n*32

    float acc[4][4][4];
#pragma unroll
    for (int mt = 0; mt < 4; mt++)
#pragma unroll
        for (int nt = 0; nt < 4; nt++)
#pragma unroll
            for (int r = 0; r < 4; r++) acc[mt][nt][r] = 0.0f;

    const int a_row = (lane & 15);
    const int a_kof = (lane >> 4) * 8;
    const int b_nl  = (lane & 7) + ((lane >> 4) << 3);
    const int b_kof = ((lane >> 3) & 1) * 8;

#pragma unroll
    for (int kk = 0; kk < 8; kk++) {
        const int k0 = kk * 16;
        uint32_t a[4][4];
#pragma unroll
        for (int mt = 0; mt < 4; mt++) {
            uint32_t ad = smb + (uint32_t)(warp_m * 64 + mt * 16 + a_row) * (APITCH * 2)
                              + (uint32_t)(k0 + a_kof) * 2;
            ldsm_x4(a[mt][0], a[mt][1], a[mt][2], a[mt][3], ad);
        }
        uint32_t bfr[2][4];
#pragma unroll
        for (int np = 0; np < 2; np++) {
            uint32_t bd = smb + S2_B_OFF
                        + (uint32_t)(warp_n * 32 + np * 16 + b_nl) * (APITCH * 2)
                        + (uint32_t)(k0 + b_kof) * 2;
            ldsm_x4(bfr[np][0], bfr[np][1], bfr[np][2], bfr[np][3], bd);
        }
#pragma unroll
        for (int mt = 0; mt < 4; mt++)
#pragma unroll
            for (int nt = 0; nt < 4; nt++)
                mma_bf16(acc[mt][nt], a[mt],
                         bfr[nt >> 1][(nt & 1) * 2 + 0],
                         bfr[nt >> 1][(nt & 1) * 2 + 1]);
    }
    __syncthreads();   // done reading A/B; reuse smem for C

    // ---- Stage C into own smem [128][CPITCH] ----
    float* Cs = reinterpret_cast<float*>(sm);
#pragma unroll
    for (int mt = 0; mt < 4; mt++) {
        const int mrow = warp_m * 64 + mt * 16 + (lane >> 2);
#pragma unroll
        for (int nt = 0; nt < 4; nt++) {
            const int ncol = warp_n * 32 + nt * 8 + (lane & 3) * 2;
            *reinterpret_cast<float2*>(&Cs[mrow * CPITCH + ncol]) =
                make_float2(acc[mt][nt][0], acc[mt][nt][1]);
            *reinterpret_cast<float2*>(&Cs[(mrow + 8) * CPITCH + ncol]) =
                make_float2(acc[mt][nt][2], acc[mt][nt][3]);
        }
    }

    // ---- Cluster barrier: all 8 siblings' C tiles ready ----
    asm volatile("barrier.cluster.arrive.aligned;" ::: "memory");
    asm volatile("barrier.cluster.wait.aligned;" ::: "memory");

    // ---- DSMEM exchange: rank owns i in [16*rank, 16*rank+16). ----
    const int e_base = (be & ~(CLU - 1)) & 63;      // e octet base
#pragma unroll
    for (int it = 0; it < 2; it++) {
        const int idx  = it * 256 + tid;            // 0..511
        const int iloc = idx >> 5;                  // 0..15
        const int j0   = (idx & 31) * 4;            // 0,4,..,124
        const int i    = (int)rank * 16 + iloc;
        const uint32_t laddr = smb + (uint32_t)(i * CPITCH + j0) * 4;

        float4 c[CLU];
#pragma unroll
        for (int s = 0; s < CLU; s++) c[s] = dsmem_ld4(laddr, (uint32_t)s);

        float* op = out + (((size_t)b * NN + i) * NN + j0) * OUTD + e_base;
#pragma unroll
        for (int jj = 0; jj < 4; jj++) {
            float v[8] = {
                (&c[0].x)[jj], (&c[1].x)[jj], (&c[2].x)[jj], (&c[3].x)[jj],
                (&c[4].x)[jj], (&c[5].x)[jj], (&c[6].x)[jj], (&c[7].x)[jj]};
            float* o = op + (size_t)jj * OUTD;
            *reinterpret_cast<float4*>(o)     = make_float4(v[0], v[1], v[2], v[3]);
            *reinterpret_cast<float4*>(o + 4) = make_float4(v[4], v[5], v[6], v[7]);
        }
    }

    // ---- Protect smem until all siblings finished reading ----
    asm volatile("barrier.cluster.arrive.aligned;" ::: "memory");
    asm volatile("barrier.cluster.wait.aligned;" ::: "memory");
}

// ---------------------------------------------------------------------------
extern "C" void kernel_launch(void* const* d_in, const int* in_sizes, int n_in,
                              void* d_out, int out_size)
{
    const float* X  = (const float*)d_in[0];
    const float* W1 = (const float*)d_in[1];
    const float* b1 = (const float*)d_in[2];
    const float* W2 = (const float*)d_in[3];
    const float* b2 = (const float*)d_in[4];
    const int*   nn = (const int*)d_in[5];
    float* out = (float*)d_out;

    __nv_bfloat16 *s1, *s2;
    cudaGetSymbolAddress((void**)&s1, g_s1);
    cudaGetSymbolAddress((void**)&s2, g_s2);

    // Fused MLP (both passes, one grid), tf32 tensor cores
    mlp_kernel<<<2 * BB * NN, 128>>>(X, W1, b1, W2, b2, nn, s1, s2);

    // Stage 2 as clusters of 8 (one e-octet per cluster)
    cudaFuncSetAttribute(stage2_kernel,
                         cudaFuncAttributeMaxDynamicSharedMemorySize, S2_SMEM);
    cudaLaunchConfig_t cfg = {};
    cfg.gridDim  = dim3(BB * OUTD, 1, 1);
    cfg.blockDim = dim3(256, 1, 1);
    cfg.dynamicSmemBytes = S2_SMEM;
    cudaLaunchAttribute attrs[1];
    attrs[0].id = cudaLaunchAttributeClusterDimension;
    attrs[0].val.clusterDim = {CLU, 1, 1};
    cfg.attrs = attrs;
    cfg.numAttrs = 1;
    cudaLaunchKernelEx(&cfg, stage2_kernel, out);
}

// round 14
// speedup vs baseline: 1.6459x; 1.0693x over previous
#include <cuda_runtime.h>
#include <cuda_bf16.h>
#include <cstdint>
#include <cstddef>

// Problem constants
#define BB   32
#define NN   128
#define IND  32
#define OUTD 64

// Scratch (device globals; no allocs allowed)
__device__ __nv_bfloat16 g_s1[(size_t)BB * OUTD * NN * NN];  // X1: [b,e,i,k]
__device__ __nv_bfloat16 g_s2[(size_t)BB * OUTD * NN * NN];  // X2^T: [b,e,j,k]

__device__ __forceinline__ uint32_t smem_u32(const void* p) {
    uint32_t a;
    asm("{ .reg .u64 t; cvta.to.shared.u64 t, %1; cvt.u32.u64 %0, t; }"
        : "=r"(a) : "l"(p));
    return a;
}
__device__ __forceinline__ float cvt_tf32(float x) {
    float r;
    asm("cvt.rna.tf32.f32 %0, %1;" : "=f"(r) : "f"(x));
    return r;
}
__device__ __forceinline__ void mma_tf32(float* c, const float* a,
                                         float b0, float b1) {
    asm volatile(
        "mma.sync.aligned.m16n8k8.row.col.f32.tf32.tf32.f32 "
        "{%0,%1,%2,%3}, {%4,%5,%6,%7}, {%8,%9}, {%0,%1,%2,%3};"
        : "+f"(c[0]), "+f"(c[1]), "+f"(c[2]), "+f"(c[3])
        : "f"(a[0]), "f"(a[1]), "f"(a[2]), "f"(a[3]), "f"(b0), "f"(b1));
}

// ---------------------------------------------------------------------------
// Fused MLP via tf32 mma (R11-proven arithmetic). Both passes in one grid.
// pass=0: block=(b,p), rows t=q, writes X1 -> s1[b,e,p,t]   (A, [i][k])
// pass=1: block=(b,q), rows t=p, writes X2 -> s2[b,e,q,t]   (B^T, [j][k])
// Grid 8192 (pass = blockIdx.x>>12), 128 threads.
// pass1 X load is cooperative/coalesced (8 threads per 128B row).
// ---------------------------------------------------------------------------
#define XP 36      // Xs pitch (floats)
#define WP 65      // Ws pitch (floats)
#define CP 136     // Cs pitch (bf16)

__global__ void __launch_bounds__(128) mlp_kernel(
    const float* __restrict__ X,
    const float* __restrict__ W1, const float* __restrict__ b1,
    const float* __restrict__ W2, const float* __restrict__ b2,
    const int* __restrict__ nn32,
    __nv_bfloat16* __restrict__ s1, __nv_bfloat16* __restrict__ s2)
{
    __shared__ float Ws[IND][WP];
    __shared__ float bs[OUTD];
    __shared__ char  ubuf[NN * XP * 4];          // Xs (18432B) / Cs (17408B)
    float*         Xs = reinterpret_cast<float*>(ubuf);
    __nv_bfloat16* Cs = reinterpret_cast<__nv_bfloat16*>(ubuf);

    const int pass = blockIdx.x >> 12;
    const int blk  = blockIdx.x & 4095;
    const int b    = blk >> 7;
    const int row  = blk & 127;
    const int tid  = threadIdx.x;
    const int wid  = tid >> 5;
    const int lane = tid & 31;

    const float* __restrict__ W    = pass ? W2 : W1;
    const float* __restrict__ bias = pass ? b2 : b1;
    __nv_bfloat16* __restrict__ dst = pass ? s2 : s1;

    for (int l = tid; l < IND * OUTD; l += 128)
        Ws[l >> 6][l & 63] = cvt_tf32(W[l]);
    if (tid < OUTD) bs[tid] = bias[tid];

    if (!pass) {
        // rows t are contiguous in gmem: thread t loads X[b,row,t,:] (coalesced)
        const int t = tid;
        const float4* Xp = reinterpret_cast<const float4*>(
            X + (((size_t)b * NN + row) * NN + t) * IND);
#pragma unroll
        for (int c = 0; c < 8; c++) {
            float4 v = Xp[c];
            float* xr = Xs + t * XP + 4 * c;
            xr[0] = cvt_tf32(v.x); xr[1] = cvt_tf32(v.y);
            xr[2] = cvt_tf32(v.z); xr[3] = cvt_tf32(v.w);
        }
    } else {
        // rows t are strided (X[b,t,row,:]): cooperative, 8 threads per row.
#pragma unroll
        for (int it = 0; it < 8; it++) {
            const int u = it * 128 + tid;       // 0..1023
            const int t = u >> 3;               // 0..127
            const int c = u & 7;                // float4 chunk
            float4 v = *reinterpret_cast<const float4*>(
                X + (((size_t)b * NN + t) * NN + row) * IND + 4 * c);
            float* xr = Xs + t * XP + 4 * c;
            xr[0] = cvt_tf32(v.x); xr[1] = cvt_tf32(v.y);
            xr[2] = cvt_tf32(v.z); xr[3] = cvt_tf32(v.w);
        }
    }
    __syncthreads();

    const int n = (nn32[1] == 0) ? nn32[2 * b] : nn32[b];   // int64 vs int32 defense
    const bool rowok = row < n;
    const int lr = lane >> 2;    // 0..7
    const int lc = lane & 3;     // 0..3

    float acc[2][8][4];
#pragma unroll
    for (int mt = 0; mt < 2; mt++)
#pragma unroll
        for (int nt = 0; nt < 8; nt++)
#pragma unroll
            for (int q = 0; q < 4; q++) acc[mt][nt][q] = 0.0f;

#pragma unroll
    for (int ks = 0; ks < 4; ks++) {
        const int k0 = ks * 8;
        float a[2][4];
#pragma unroll
        for (int mt = 0; mt < 2; mt++) {
            const int r0 = 32 * wid + 16 * mt + lr;
            a[mt][0] = Xs[r0 * XP + k0 + lc];
            a[mt][1] = Xs[(r0 + 8) * XP + k0 + lc];
            a[mt][2] = Xs[r0 * XP + k0 + 4 + lc];
            a[mt][3] = Xs[(r0 + 8) * XP + k0 + 4 + lc];
        }
        float bfr[8][2];
#pragma unroll
        for (int nt = 0; nt < 8; nt++) {
            const int n0 = 8 * nt + lr;
            bfr[nt][0] = Ws[k0 + lc][n0];
            bfr[nt][1] = Ws[k0 + 4 + lc][n0];
        }
#pragma unroll
        for (int mt = 0; mt < 2; mt++)
#pragma unroll
            for (int nt = 0; nt < 8; nt++)
                mma_tf32(acc[mt][nt], a[mt], bfr[nt][0], bfr[nt][1]);
    }
    __syncthreads();   // done with Xs; reuse as Cs

    // ---- bias + ReLU + mask, stage bf16 into Cs[e][t] ----
#pragma unroll
    for (int mt = 0; mt < 2; mt++) {
        const int r_lo = 32 * wid + 16 * mt + lr;
        const int r_hi = r_lo + 8;
        const float mlo = (rowok && r_lo < n) ? 1.0f : 0.0f;
        const float mhi = (rowok && r_hi < n) ? 1.0f : 0.0f;
#pragma unroll
        for (int nt = 0; nt < 8; nt++) {
            const int e0 = 8 * nt + 2 * lc;
            const float bb0 = bs[e0], bb1 = bs[e0 + 1];
            Cs[e0 * CP + r_lo]       = __float2bfloat16(fmaxf(acc[mt][nt][0] + bb0, 0.0f) * mlo);
            Cs[(e0 + 1) * CP + r_lo] = __float2bfloat16(fmaxf(acc[mt][nt][1] + bb1, 0.0f) * mlo);
            Cs[e0 * CP + r_hi]       = __float2bfloat16(fmaxf(acc[mt][nt][2] + bb0, 0.0f) * mhi);
            Cs[(e0 + 1) * CP + r_hi] = __float2bfloat16(fmaxf(acc[mt][nt][3] + bb1, 0.0f) * mhi);
        }
    }
    __syncthreads();

    // ---- coalesced gmem store: dst[b,e,row,t], 16B chunks ----
    __nv_bfloat16* dbase = dst + (size_t)(b * OUTD) * (NN * NN) + (size_t)row * NN;
#pragma unroll
    for (int it = 0; it < 8; it++) {
        const int u   = it * 128 + tid;        // 0..1023
        const int e   = u >> 4;
        const int c16 = u & 15;                // 16B chunk (8 bf16)
        *reinterpret_cast<uint4*>(dbase + (size_t)e * (NN * NN) + c16 * 8) =
            *reinterpret_cast<const uint4*>(Cs + e * CP + c16 * 8);
    }
}

// ---------------------------------------------------------------------------
// Stage 2 (R11-proven fragment paths): 2048 x [128x128x128] bf16 mma.sync
// GEMMs, one CTA per (b,e), clusters of 8 = one e-octet. A [i][k], B^T [j][k],
// both non-trans ldmatrix. Loads via cp.async. DSMEM exchange assembles
// out[b,i,j,e0:e0+8] directly.
// ---------------------------------------------------------------------------
#define APITCH 136                       // bf16/row: 272B, 16B-aligned, LDSM conflict-free
#define S2_B_OFF (NN * APITCH * 2)       // 34816 B
#define CPITCH 132                       // fp32/row for C staging
#define S2_SMEM (2 * NN * APITCH * 2)    // 69632 B (>= C staging 67584)
#define CLU 8

__device__ __forceinline__ void cp_async16(uint32_t smem_addr, const void* gptr) {
    asm volatile("cp.async.cg.shared.global [%0], [%1], 16;"
                 :: "r"(smem_addr), "l"(gptr));
}
__device__ __forceinline__ void ldsm_x4(uint32_t& r0, uint32_t& r1,
                                        uint32_t& r2, uint32_t& r3, uint32_t a) {
    asm volatile("ldmatrix.sync.aligned.m8n8.x4.shared.b16 {%0,%1,%2,%3}, [%4];"
                 : "=r"(r0), "=r"(r1), "=r"(r2), "=r"(r3) : "r"(a));
}
__device__ __forceinline__ void mma_bf16(float* c, const uint32_t* a,
                                         uint32_t b0, uint32_t b1) {
    asm volatile(
        "mma.sync.aligned.m16n8k16.row.col.f32.bf16.bf16.f32 "
        "{%0,%1,%2,%3}, {%4,%5,%6,%7}, {%8,%9}, {%0,%1,%2,%3};"
        : "+f"(c[0]), "+f"(c[1]), "+f"(c[2]), "+f"(c[3])
        : "r"(a[0]), "r"(a[1]), "r"(a[2]), "r"(a[3]), "r"(b0), "r"(b1));
}
__device__ __forceinline__ float4 dsmem_ld4(uint32_t local_addr, uint32_t rank) {
    uint32_t r; float4 v;
    asm volatile("mapa.shared::cluster.u32 %0, %1, %2;"
                 : "=r"(r) : "r"(local_addr), "r"(rank));
    asm volatile("ld.shared::cluster.v4.f32 {%0,%1,%2,%3}, [%4];"
                 : "=f"(v.x), "=f"(v.y), "=f"(v.z), "=f"(v.w) : "r"(r));
    return v;
}

__global__ void __launch_bounds__(256, 1) stage2_kernel(float* __restrict__ out)
{
    extern __shared__ char sm[];
    const uint32_t smb = smem_u32(sm);
    const int tid  = threadIdx.x;
    const int wid  = tid >> 5;
    const int lane = tid & 31;
    const int be   = blockIdx.x;
    const int b    = be >> 6;
    uint32_t rank;
    asm("mov.u32 %0, %%cluster_ctarank;" : "=r"(rank));

    // ---- Load A [i][k] and B^T [j][k] tiles via cp.async ----
    const uint4* A4 = reinterpret_cast<const uint4*>(g_s1 + (size_t)be * (NN * NN));
    const uint4* B4 = reinterpret_cast<const uint4*>(g_s2 + (size_t)be * (NN * NN));
#pragma unroll
    for (int it = 0; it < 8; it++) {
        const int l = it * 256 + tid;          // 2048 uint4 per operand
        const int r = l >> 4, c8 = l & 15;
        const uint32_t o = (uint32_t)r * (APITCH * 2) + (uint32_t)c8 * 16;
        cp_async16(smb + o,            A4 + l);
        cp_async16(smb + S2_B_OFF + o, B4 + l);
    }
    asm volatile("cp.async.commit_group;" ::: "memory");
    asm volatile("cp.async.wait_group 0;" ::: "memory");
    __syncthreads();

    const int warp_m = wid >> 2;   // rows warp_m*64
    const int warp_n = wid & 3;    // cols warp_n*32

    float acc[4][4][4];
#pragma unroll
    for (int mt = 0; mt < 4; mt++)
#pragma unroll
        for (int nt = 0; nt < 4; nt++)
#pragma unroll
            for (int r = 0; r < 4; r++) acc[mt][nt][r] = 0.0f;

    const int a_row = (lane & 15);
    const int a_kof = (lane >> 4) * 8;
    const int b_nl  = (lane & 7) + ((lane >> 4) << 3);
    const int b_kof = ((lane >> 3) & 1) * 8;

#pragma unroll
    for (int kk = 0; kk < 8; kk++) {
        const int k0 = kk * 16;
        uint32_t a[4][4];
#pragma unroll
        for (int mt = 0; mt < 4; mt++) {
            uint32_t ad = smb + (uint32_t)(warp_m * 64 + mt * 16 + a_row) * (APITCH * 2)
                              + (uint32_t)(k0 + a_kof) * 2;
            ldsm_x4(a[mt][0], a[mt][1], a[mt][2], a[mt][3], ad);
        }
        uint32_t bfr[2][4];
#pragma unroll
        for (int np = 0; np < 2; np++) {
            uint32_t bd = smb + S2_B_OFF
                        + (uint32_t)(warp_n * 32 + np * 16 + b_nl) * (APITCH * 2)
                        + (uint32_t)(k0 + b_kof) * 2;
            ldsm_x4(bfr[np][0], bfr[np][1], bfr[np][2], bfr[np][3], bd);
        }
#pragma unroll
        for (int mt = 0; mt < 4; mt++)
#pragma unroll
            for (int nt = 0; nt < 4; nt++)
                mma_bf16(acc[mt][nt], a[mt],
                         bfr[nt >> 1][(nt & 1) * 2 + 0],
                         bfr[nt >> 1][(nt & 1) * 2 + 1]);
    }
    __syncthreads();   // done reading A/B; reuse smem for C

    // ---- Stage C into own smem [128][CPITCH] ----
    float* Cs = reinterpret_cast<float*>(sm);
#pragma unroll
    for (int mt = 0; mt < 4; mt++) {
        const int mrow = warp_m * 64 + mt * 16 + (lane >> 2);
#pragma unroll
        for (int nt = 0; nt < 4; nt++) {
            const int ncol = warp_n * 32 + nt * 8 + (lane & 3) * 2;
            *reinterpret_cast<float2*>(&Cs[mrow * CPITCH + ncol]) =
                make_float2(acc[mt][nt][0], acc[mt][nt][1]);
            *reinterpret_cast<float2*>(&Cs[(mrow + 8) * CPITCH + ncol]) =
                make_float2(acc[mt][nt][2], acc[mt][nt][3]);
        }
    }

    // ---- Cluster barrier: all 8 siblings' C tiles ready ----
    asm volatile("barrier.cluster.arrive.aligned;" ::: "memory");
    asm volatile("barrier.cluster.wait.aligned;" ::: "memory");

    // ---- DSMEM exchange: rank owns i in [16*rank, 16*rank+16). ----
    const int e_base = (be & ~(CLU - 1)) & 63;      // e octet base
#pragma unroll
    for (int it = 0; it < 2; it++) {
        const int idx  = it * 256 + tid;            // 0..511
        const int iloc = idx >> 5;                  // 0..15
        const int j0   = (idx & 31) * 4;            // 0,4,..,124
        const int i    = (int)rank * 16 + iloc;
        const uint32_t laddr = smb + (uint32_t)(i * CPITCH + j0) * 4;

        float4 c[CLU];
#pragma unroll
        for (int s = 0; s < CLU; s++) c[s] = dsmem_ld4(laddr, (uint32_t)s);

        float* op = out + (((size_t)b * NN + i) * NN + j0) * OUTD + e_base;
#pragma unroll
        for (int jj = 0; jj < 4; jj++) {
            float v[8] = {
                (&c[0].x)[jj], (&c[1].x)[jj], (&c[2].x)[jj], (&c[3].x)[jj],
                (&c[4].x)[jj], (&c[5].x)[jj], (&c[6].x)[jj], (&c[7].x)[jj]};
            float* o = op + (size_t)jj * OUTD;
            *reinterpret_cast<float4*>(o)     = make_float4(v[0], v[1], v[2], v[3]);
            *reinterpret_cast<float4*>(o + 4) = make_float4(v[4], v[5], v[6], v[7]);
        }
    }

    // ---- Protect smem until all siblings finished reading ----
    asm volatile("barrier.cluster.arrive.aligned;" ::: "memory");
    asm volatile("barrier.cluster.wait.aligned;" ::: "memory");
}

// ---------------------------------------------------------------------------
extern "C" void kernel_launch(void* const* d_in, const int* in_sizes, int n_in,
                              void* d_out, int out_size)
{
    const float* X  = (const float*)d_in[0];
    const float* W1 = (const float*)d_in[1];
    const float* b1 = (const float*)d_in[2];
    const float* W2 = (const float*)d_in[3];
    const float* b2 = (const float*)d_in[4];
    const int*   nn = (const int*)d_in[5];
    float* out = (float*)d_out;

    __nv_bfloat16 *s1, *s2;
    cudaGetSymbolAddress((void**)&s1, g_s1);
    cudaGetSymbolAddress((void**)&s2, g_s2);

    // Fused two-pass MLP (one grid), tf32 tensor cores
    mlp_kernel<<<2 * BB * NN, 128>>>(X, W1, b1, W2, b2, nn, s1, s2);

    // Stage 2 as clusters of 8 (one e-octet per cluster)
    cudaFuncSetAttribute(stage2_kernel,
                         cudaFuncAttributeMaxDynamicSharedMemorySize, S2_SMEM);
    cudaLaunchConfig_t cfg = {};
    cfg.gridDim  = dim3(BB * OUTD, 1, 1);
    cfg.blockDim = dim3(256, 1, 1);
    cfg.dynamicSmemBytes = S2_SMEM;
    cudaLaunchAttribute attrs[1];
    attrs[0].id = cudaLaunchAttributeClusterDimension;
    attrs[0].val.clusterDim = {CLU, 1, 1};
    cfg.attrs = attrs;
    cfg.numAttrs = 1;
    cudaLaunchKernelEx(&cfg, stage2_kernel, out);
}

// round 17
// speedup vs baseline: 1.7431x; 1.0591x over previous
#include <cuda_runtime.h>
#include <cuda_bf16.h>
#include <cstdint>
#include <cstddef>

// Problem constants
#define BB   32
#define NN   128
#define IND  32
#define OUTD 64

// Scratch (device globals; no allocs allowed)
__device__ __nv_bfloat16 g_s1[(size_t)BB * OUTD * NN * NN];  // X1: [b,e,i,k]
__device__ __nv_bfloat16 g_s2[(size_t)BB * OUTD * NN * NN];  // X2^T: [b,e,j,k]

__device__ __forceinline__ uint32_t smem_u32(const void* p) {
    uint32_t a;
    asm("{ .reg .u64 t; cvta.to.shared.u64 t, %1; cvt.u32.u64 %0, t; }"
        : "=r"(a) : "l"(p));
    return a;
}
__device__ __forceinline__ float cvt_tf32(float x) {
    float r;
    asm("cvt.rna.tf32.f32 %0, %1;" : "=f"(r) : "f"(x));
    return r;
}
__device__ __forceinline__ void mma_tf32(float* c, const float* a,
                                         float b0, float b1) {
    asm volatile(
        "mma.sync.aligned.m16n8k8.row.col.f32.tf32.tf32.f32 "
        "{%0,%1,%2,%3}, {%4,%5,%6,%7}, {%8,%9}, {%0,%1,%2,%3};"
        : "+f"(c[0]), "+f"(c[1]), "+f"(c[2]), "+f"(c[3])
        : "f"(a[0]), "f"(a[1]), "f"(a[2]), "f"(a[3]), "f"(b0), "f"(b1));
}

// ---------------------------------------------------------------------------
// Fused MLP via tf32 mma (R14-proven arithmetic). Both passes in one grid.
// pass=0: block=(b,p), rows t=q, writes X1 -> s1[b,e,p,t]   (A, [i][k])
// pass=1: block=(b,q), rows t=p, writes X2 -> s2[b,e,q,t]   (B^T, [j][k])
// Grid 8192 (pass = blockIdx.x>>12), 128 threads.
// WP=72: >= OUTD (no overflow!) and 72 mod 32 = 8 -> B-frag gather banks
// (72*lc + lr) mod 32 = 8*lc + lr, all 32 distinct (conflict-free).
// ---------------------------------------------------------------------------
#define XP 36      // Xs pitch (floats): A-frag banks 4*lr+lc, distinct
#define WP 72      // Ws pitch (floats): >=64 and ==8 (mod 32)
#define CP 136     // Cs pitch (bf16)

__global__ void __launch_bounds__(128) mlp_kernel(
    const float* __restrict__ X,
    const float* __restrict__ W1, const float* __restrict__ b1,
    const float* __restrict__ W2, const float* __restrict__ b2,
    const int* __restrict__ nn32,
    __nv_bfloat16* __restrict__ s1, __nv_bfloat16* __restrict__ s2)
{
    __shared__ float Ws[IND][WP];
    __shared__ float bs[OUTD];
    __shared__ char  ubuf[NN * XP * 4];          // Xs (18432B) / Cs (17408B)
    float*         Xs = reinterpret_cast<float*>(ubuf);
    __nv_bfloat16* Cs = reinterpret_cast<__nv_bfloat16*>(ubuf);

    const int pass = blockIdx.x >> 12;
    const int blk  = blockIdx.x & 4095;
    const int b    = blk >> 7;
    const int row  = blk & 127;
    const int tid  = threadIdx.x;
    const int wid  = tid >> 5;
    const int lane = tid & 31;

    const float* __restrict__ W    = pass ? W2 : W1;
    const float* __restrict__ bias = pass ? b2 : b1;
    __nv_bfloat16* __restrict__ dst = pass ? s2 : s1;

    for (int l = tid; l < IND * OUTD; l += 128)
        Ws[l >> 6][l & 63] = cvt_tf32(W[l]);
    if (tid < OUTD) bs[tid] = bias[tid];

    if (!pass) {
        // rows t are contiguous in gmem: thread t loads X[b,row,t,:] (coalesced)
        const int t = tid;
        const float4* Xp = reinterpret_cast<const float4*>(
            X + (((size_t)b * NN + row) * NN + t) * IND);
#pragma unroll
        for (int c = 0; c < 8; c++) {
            float4 v = Xp[c];
            float* xr = Xs + t * XP + 4 * c;
            xr[0] = cvt_tf32(v.x); xr[1] = cvt_tf32(v.y);
            xr[2] = cvt_tf32(v.z); xr[3] = cvt_tf32(v.w);
        }
    } else {
        // rows t are strided (X[b,t,row,:]): cooperative, 8 threads per row.
#pragma unroll
        for (int it = 0; it < 8; it++) {
            const int u = it * 128 + tid;       // 0..1023
            const int t = u >> 3;               // 0..127
            const int c = u & 7;                // float4 chunk
            float4 v = *reinterpret_cast<const float4*>(
                X + (((size_t)b * NN + t) * NN + row) * IND + 4 * c);
            float* xr = Xs + t * XP + 4 * c;
            xr[0] = cvt_tf32(v.x); xr[1] = cvt_tf32(v.y);
            xr[2] = cvt_tf32(v.z); xr[3] = cvt_tf32(v.w);
        }
    }
    __syncthreads();

    const int n = (nn32[1] == 0) ? nn32[2 * b] : nn32[b];   // int64 vs int32 defense
    const bool rowok = row < n;
    const int lr = lane >> 2;    // 0..7
    const int lc = lane & 3;     // 0..3

    float acc[2][8][4];
#pragma unroll
    for (int mt = 0; mt < 2; mt++)
#pragma unroll
        for (int nt = 0; nt < 8; nt++)
#pragma unroll
            for (int q = 0; q < 4; q++) acc[mt][nt][q] = 0.0f;

#pragma unroll
    for (int ks = 0; ks < 4; ks++) {
        const int k0 = ks * 8;
        float a[2][4];
#pragma unroll
        for (int mt = 0; mt < 2; mt++) {
            const int r0 = 32 * wid + 16 * mt + lr;
            a[mt][0] = Xs[r0 * XP + k0 + lc];
            a[mt][1] = Xs[(r0 + 8) * XP + k0 + lc];
            a[mt][2] = Xs[r0 * XP + k0 + 4 + lc];
            a[mt][3] = Xs[(r0 + 8) * XP + k0 + 4 + lc];
        }
        float bfr[8][2];
#pragma unroll
        for (int nt = 0; nt < 8; nt++) {
            const int n0 = 8 * nt + lr;
            bfr[nt][0] = Ws[k0 + lc][n0];
            bfr[nt][1] = Ws[k0 + 4 + lc][n0];
        }
#pragma unroll
        for (int mt = 0; mt < 2; mt++)
#pragma unroll
            for (int nt = 0; nt < 8; nt++)
                mma_tf32(acc[mt][nt], a[mt], bfr[nt][0], bfr[nt][1]);
    }
    __syncthreads();   // done with Xs; reuse as Cs

    // ---- bias + ReLU + mask, stage bf16 into Cs[e][t] ----
#pragma unroll
    for (int mt = 0; mt < 2; mt++) {
        const int r_lo = 32 * wid + 16 * mt + lr;
        const int r_hi = r_lo + 8;
        const float mlo = (rowok && r_lo < n) ? 1.0f : 0.0f;
        const float mhi = (rowok && r_hi < n) ? 1.0f : 0.0f;
#pragma unroll
        for (int nt = 0; nt < 8; nt++) {
            const int e0 = 8 * nt + 2 * lc;
            const float bb0 = bs[e0], bb1 = bs[e0 + 1];
            Cs[e0 * CP + r_lo]       = __float2bfloat16(fmaxf(acc[mt][nt][0] + bb0, 0.0f) * mlo);
            Cs[(e0 + 1) * CP + r_lo] = __float2bfloat16(fmaxf(acc[mt][nt][1] + bb1, 0.0f) * mlo);
            Cs[e0 * CP + r_hi]       = __float2bfloat16(fmaxf(acc[mt][nt][2] + bb0, 0.0f) * mhi);
            Cs[(e0 + 1) * CP + r_hi] = __float2bfloat16(fmaxf(acc[mt][nt][3] + bb1, 0.0f) * mhi);
        }
    }
    __syncthreads();

    // ---- coalesced gmem store: dst[b,e,row,t], 16B chunks ----
    __nv_bfloat16* dbase = dst + (size_t)(b * OUTD) * (NN * NN) + (size_t)row * NN;
#pragma unroll
    for (int it = 0; it < 8; it++) {
        const int u   = it * 128 + tid;        // 0..1023
        const int e   = u >> 4;
        const int c16 = u & 15;                // 16B chunk (8 bf16)
        *reinterpret_cast<uint4*>(dbase + (size_t)e * (NN * NN) + c16 * 8) =
            *reinterpret_cast<const uint4*>(Cs + e * CP + c16 * 8);
    }
}

// ---------------------------------------------------------------------------
// Stage 2 (R14-proven, byte-identical): 2048 x [128x128x128] bf16 mma.sync
// GEMMs, one CTA per (b,e), clusters of 8 = one e-octet. A [i][k], B^T [j][k],
// both non-trans ldmatrix. Loads via cp.async. DSMEM exchange assembles
// out[b,i,j,e0:e0+8] directly.
// ---------------------------------------------------------------------------
#define APITCH 136                       // bf16/row: 272B, 16B-aligned, LDSM conflict-free
#define S2_B_OFF (NN * APITCH * 2)       // 34816 B
#define CPITCH 132                       // fp32/row for C staging
#define S2_SMEM (2 * NN * APITCH * 2)    // 69632 B (>= C staging 67584)
#define CLU 8

__device__ __forceinline__ void cp_async16(uint32_t smem_addr, const void* gptr) {
    asm volatile("cp.async.cg.shared.global [%0], [%1], 16;"
                 :: "r"(smem_addr), "l"(gptr));
}
__device__ __forceinline__ void ldsm_x4(uint32_t& r0, uint32_t& r1,
                                        uint32_t& r2, uint32_t& r3, uint32_t a) {
    asm volatile("ldmatrix.sync.aligned.m8n8.x4.shared.b16 {%0,%1,%2,%3}, [%4];"
                 : "=r"(r0), "=r"(r1), "=r"(r2), "=r"(r3) : "r"(a));
}
__device__ __forceinline__ void mma_bf16(float* c, const uint32_t* a,
                                         uint32_t b0, uint32_t b1) {
    asm volatile(
        "mma.sync.aligned.m16n8k16.row.col.f32.bf16.bf16.f32 "
        "{%0,%1,%2,%3}, {%4,%5,%6,%7}, {%8,%9}, {%0,%1,%2,%3};"
        : "+f"(c[0]), "+f"(c[1]), "+f"(c[2]), "+f"(c[3])
        : "r"(a[0]), "r"(a[1]), "r"(a[2]), "r"(a[3]), "r"(b0), "r"(b1));
}
__device__ __forceinline__ float4 dsmem_ld4(uint32_t local_addr, uint32_t rank) {
    uint32_t r; float4 v;
    asm volatile("mapa.shared::cluster.u32 %0, %1, %2;"
                 : "=r"(r) : "r"(local_addr), "r"(rank));
    asm volatile("ld.shared::cluster.v4.f32 {%0,%1,%2,%3}, [%4];"
                 : "=f"(v.x), "=f"(v.y), "=f"(v.z), "=f"(v.w) : "r"(r));
    return v;
}

__global__ void __launch_bounds__(256, 1) stage2_kernel(float* __restrict__ out)
{
    extern __shared__ char sm[];
    const uint32_t smb = smem_u32(sm);
    const int tid  = threadIdx.x;
    const int wid  = tid >> 5;
    const int lane = tid & 31;
    const int be   = blockIdx.x;
    const int b    = be >> 6;
    uint32_t rank;
    asm("mov.u32 %0, %%cluster_ctarank;" : "=r"(rank));

    // ---- Load A [i][k] and B^T [j][k] tiles via cp.async ----
    const uint4* A4 = reinterpret_cast<const uint4*>(g_s1 + (size_t)be * (NN * NN));
    const uint4* B4 = reinterpret_cast<const uint4*>(g_s2 + (size_t)be * (NN * NN));
#pragma unroll
    for (int it = 0; it < 8; it++) {
        const int l = it * 256 + tid;          // 2048 uint4 per operand
        const int r = l >> 4, c8 = l & 15;
        const uint32_t o = (uint32_t)r * (APITCH * 2) + (uint32_t)c8 * 16;
        cp_async16(smb + o,            A4 + l);
        cp_async16(smb + S2_B_OFF + o, B4 + l);
    }
    asm volatile("cp.async.commit_group;" ::: "memory");
    asm volatile("cp.async.wait_group 0;" ::: "memory");
    __syncthreads();

    const int warp_m = wid >> 2;   // rows warp_m*64
    const int warp_n = wid & 3;    // cols warp_n*32

    float acc[4][4][4];
#pragma unroll
    for (int mt = 0; mt < 4; mt++)
#pragma unroll
        for (int nt = 0; nt < 4; nt++)
#pragma unroll
            for (int r = 0; r < 4; r++) acc[mt][nt][r] = 0.0f;

    const int a_row = (lane & 15);
    const int a_kof = (lane >> 4) * 8;
    const int b_nl  = (lane & 7) + ((lane >> 4) << 3);
    const int b_kof = ((lane >> 3) & 1) * 8;

#pragma unroll
    for (int kk = 0; kk < 8; kk++) {
        const int k0 = kk * 16;
        uint32_t a[4][4];
#pragma unroll
        for (int mt = 0; mt < 4; mt++) {
            uint32_t ad = smb + (uint32_t)(warp_m * 64 + mt * 16 + a_row) * (APITCH * 2)
                              + (uint32_t)(k0 + a_kof) * 2;
            ldsm_x4(a[mt][0], a[mt][1], a[mt][2], a[mt][3], ad);
        }
        uint32_t bfr[2][4];
#pragma unroll
        for (int np = 0; np < 2; np++) {
            uint32_t bd = smb + S2_B_OFF
                        + (uint32_t)(warp_n * 32 + np * 16 + b_nl) * (APITCH * 2)
                        + (uint32_t)(k0 + b_kof) * 2;
            ldsm_x4(bfr[np][0], bfr[np][1], bfr[np][2], bfr[np][3], bd);
        }
#pragma unroll
        for (int mt = 0; mt < 4; mt++)
#pragma unroll
            for (int nt = 0; nt < 4; nt++)
                mma_bf16(acc[mt][nt], a[mt],
                         bfr[nt >> 1][(nt & 1) * 2 + 0],
                         bfr[nt >> 1][(nt & 1) * 2 + 1]);
    }
    __syncthreads();   // done reading A/B; reuse smem for C

    // ---- Stage C into own smem [128][CPITCH] ----
    float* Cs = reinterpret_cast<float*>(sm);
#pragma unroll
    for (int mt = 0; mt < 4; mt++) {
        const int mrow = warp_m * 64 + mt * 16 + (lane >> 2);
#pragma unroll
        for (int nt = 0; nt < 4; nt++) {
            const int ncol = warp_n * 32 + nt * 8 + (lane & 3) * 2;
            *reinterpret_cast<float2*>(&Cs[mrow * CPITCH + ncol]) =
                make_float2(acc[mt][nt][0], acc[mt][nt][1]);
            *reinterpret_cast<float2*>(&Cs[(mrow + 8) * CPITCH + ncol]) =
                make_float2(acc[mt][nt][2], acc[mt][nt][3]);
        }
    }

    // ---- Cluster barrier: all 8 siblings' C tiles ready ----
    asm volatile("barrier.cluster.arrive.aligned;" ::: "memory");
    asm volatile("barrier.cluster.wait.aligned;" ::: "memory");

    // ---- DSMEM exchange: rank owns i in [16*rank, 16*rank+16). ----
    const int e_base = (be & ~(CLU - 1)) & 63;      // e octet base
#pragma unroll
    for (int it = 0; it < 2; it++) {
        const int idx  = it * 256 + tid;            // 0..511
        const int iloc = idx >> 5;                  // 0..15
        const int j0   = (idx & 31) * 4;            // 0,4,..,124
        const int i    = (int)rank * 16 + iloc;
        const uint32_t laddr = smb + (uint32_t)(i * CPITCH + j0) * 4;

        float4 c[CLU];
#pragma unroll
        for (int s = 0; s < CLU; s++) c[s] = dsmem_ld4(laddr, (uint32_t)s);

        float* op = out + (((size_t)b * NN + i) * NN + j0) * OUTD + e_base;
#pragma unroll
        for (int jj = 0; jj < 4; jj++) {
            float v[8] = {
                (&c[0].x)[jj], (&c[1].x)[jj], (&c[2].x)[jj], (&c[3].x)[jj],
                (&c[4].x)[jj], (&c[5].x)[jj], (&c[6].x)[jj], (&c[7].x)[jj]};
            float* o = op + (size_t)jj * OUTD;
            *reinterpret_cast<float4*>(o)     = make_float4(v[0], v[1], v[2], v[3]);
            *reinterpret_cast<float4*>(o + 4) = make_float4(v[4], v[5], v[6], v[7]);
        }
    }

    // ---- Protect smem until all siblings finished reading ----
    asm volatile("barrier.cluster.arrive.aligned;" ::: "memory");
    asm volatile("barrier.cluster.wait.aligned;" ::: "memory");
}

// ---------------------------------------------------------------------------
extern "C" void kernel_launch(void* const* d_in, const int* in_sizes, int n_in,
                              void* d_out, int out_size)
{
    const float* X  = (const float*)d_in[0];
    const float* W1 = (const float*)d_in[1];
    const float* b1 = (const float*)d_in[2];
    const float* W2 = (const float*)d_in[3];
    const float* b2 = (const float*)d_in[4];
    const int*   nn = (const int*)d_in[5];
    float* out = (float*)d_out;

    __nv_bfloat16 *s1, *s2;
    cudaGetSymbolAddress((void**)&s1, g_s1);
    cudaGetSymbolAddress((void**)&s2, g_s2);

    // Fused two-pass MLP (one grid), tf32 tensor cores
    mlp_kernel<<<2 * BB * NN, 128>>>(X, W1, b1, W2, b2, nn, s1, s2);

    // Stage 2 as clusters of 8 (one e-octet per cluster)
    cudaFuncSetAttribute(stage2_kernel,
                         cudaFuncAttributeMaxDynamicSharedMemorySize, S2_SMEM);
    cudaLaunchConfig_t cfg = {};
    cfg.gridDim  = dim3(BB * OUTD, 1, 1);
    cfg.blockDim = dim3(256, 1, 1);
    cfg.dynamicSmemBytes = S2_SMEM;
    cudaLaunchAttribute attrs[1];
    attrs[0].id = cudaLaunchAttributeClusterDimension;
    attrs[0].val.clusterDim = {CLU, 1, 1};
    cfg.attrs = attrs;
    cfg.numAttrs = 1;
    cudaLaunchKernelEx(&cfg, stage2_kernel, out);
}